// round 1
// baseline (speedup 1.0000x reference)
#include <cuda_runtime.h>

#define ED  256
#define NH  8
#define NP  8
#define D   32
#define EPSF 1e-5f
#define MAXB 8

// Per-batch precomputed sampling offsets (post-relu) and softmaxed attention weights.
__device__ float g_off[MAXB * NH * NP * 2];  // [b][head][pt][xy]
__device__ float g_aw [MAXB * NH * NP];      // [b][head][pt]

// ---------------------------------------------------------------------------
// Precompute: off = relu(q @ W_off + b_off), aw = softmax_p(relu(q @ W_attn + b_attn))
// One block per batch; query is broadcast so this is per-batch only.
// ---------------------------------------------------------------------------
__global__ void sca_precompute_kernel(const float* __restrict__ query,
                                      const float* __restrict__ W_off,
                                      const float* __restrict__ b_off,
                                      const float* __restrict__ W_attn,
                                      const float* __restrict__ b_attn) {
    const int b = blockIdx.x;
    const int t = threadIdx.x;  // 0..255
    __shared__ float sq[ED];
    __shared__ float sa[NH * NP];

    sq[t] = query[b * ED + t];
    __syncthreads();

    if (t < NH * NP * 2) {
        float acc = b_off[t];
        #pragma unroll 8
        for (int k = 0; k < ED; k++)
            acc = fmaf(sq[k], W_off[k * (NH * NP * 2) + t], acc);
        g_off[b * NH * NP * 2 + t] = fmaxf(acc, 0.0f);
    }
    if (t < NH * NP) {
        float acc = b_attn[t];
        #pragma unroll 8
        for (int k = 0; k < ED; k++)
            acc = fmaf(sq[k], W_attn[k * (NH * NP) + t], acc);
        sa[t] = fmaxf(acc, 0.0f);
    }
    __syncthreads();

    if (t < NH * NP) {
        const int g = t & ~(NP - 1);
        float m = -1e30f;
        #pragma unroll
        for (int i = 0; i < NP; i++) m = fmaxf(m, sa[g + i]);
        float s = 0.0f;
        #pragma unroll
        for (int i = 0; i < NP; i++) s += expf(sa[g + i] - m);
        g_aw[b * NH * NP + t] = expf(sa[t] - m) / s;
    }
}

// ---------------------------------------------------------------------------
// Main: bilinear gather + weighted sum + residual + LayerNorm.
// Grid: (nq, bs). Block: 256 = 8 warps (one per head), lane = channel.
// ---------------------------------------------------------------------------
__global__ __launch_bounds__(256) void sca_main_kernel(
    const float* __restrict__ query,   // [bs, ED]
    const float* __restrict__ feat,    // [bs, nq, NH, D]
    const float* __restrict__ ref2d,   // [bs, nq, 2]
    const float* __restrict__ ln_g,
    const float* __restrict__ ln_b,
    const int*   __restrict__ hp,
    const int*   __restrict__ wp,
    float* __restrict__ out,           // [bs, nq, ED]
    int nq)
{
    const int q    = blockIdx.x;
    const int b    = blockIdx.y;
    const int t    = threadIdx.x;
    const int head = t >> 5;
    const int lane = t & 31;

    const int w = *wp;
    const int h = *hp;

    __shared__ float s_off[NH * NP * 2];
    __shared__ float s_aw [NH * NP];
    __shared__ float s_ref[2];
    __shared__ float s_red[2 * NH];

    if (t < NH * NP * 2) s_off[t] = g_off[b * NH * NP * 2 + t];
    if (t < NH * NP)     s_aw[t]  = g_aw [b * NH * NP + t];
    if (t < 2)           s_ref[t] = ref2d[((long)b * nq + q) * 2 + t];
    __syncthreads();

    const float rx = s_ref[0];
    const float ry = s_ref[1];
    const float fw = (float)w;
    const float fh = (float)h;
    const float inv_w = 1.0f / fw;
    const float inv_h = 1.0f / fh;

    // base pointer for this (batch, head, channel)
    const float* fbase = feat + (((long)b * nq) * NH + head) * D + lane;
    const int row_stride = NH * D;        // stride for +1 in x
    const int col_stride = w * NH * D;    // stride for +1 in y

    float acc = 0.0f;
    #pragma unroll
    for (int p = 0; p < NP; p++) {
        const float offx = s_off[(head * NP + p) * 2 + 0];
        const float offy = s_off[(head * NP + p) * 2 + 1];
        const float aw   = s_aw[head * NP + p];

        // loc = ref + off/normalizer ; pixel = loc*dim - 0.5
        const float x = fmaf(offx, inv_w, rx) * fw - 0.5f;
        const float y = fmaf(offy, inv_h, ry) * fh - 0.5f;

        const float x0f = floorf(x);
        const float y0f = floorf(y);
        const float fx = x - x0f;
        const float fy = y - y0f;
        const int x0 = (int)x0f;
        const int y0 = (int)y0f;
        const int x1 = x0 + 1;
        const int y1 = y0 + 1;

        const bool vx0 = (x0 >= 0) & (x0 < w);
        const bool vx1 = (x1 >= 0) & (x1 < w);
        const bool vy0 = (y0 >= 0) & (y0 < h);
        const bool vy1 = (y1 >= 0) & (y1 < h);

        const int cx0 = min(max(x0, 0), w - 1);
        const int cx1 = min(max(x1, 0), w - 1);
        const int cy0 = min(max(y0, 0), h - 1);
        const int cy1 = min(max(y1, 0), h - 1);

        float s00 = 0.0f, s01 = 0.0f, s10 = 0.0f, s11 = 0.0f;
        if (vy0 & vx0) s00 = __ldg(fbase + cy0 * col_stride + cx0 * row_stride);
        if (vy0 & vx1) s01 = __ldg(fbase + cy0 * col_stride + cx1 * row_stride);
        if (vy1 & vx0) s10 = __ldg(fbase + cy1 * col_stride + cx0 * row_stride);
        if (vy1 & vx1) s11 = __ldg(fbase + cy1 * col_stride + cx1 * row_stride);

        const float top = s00 * (1.0f - fx) + s01 * fx;
        const float bot = s10 * (1.0f - fx) + s11 * fx;
        acc = fmaf(aw, top * (1.0f - fy) + bot * fy, acc);
    }

    // residual with broadcast query
    const float res = acc + query[b * ED + t];

    // LayerNorm over ED=256 (8 warps)
    float v  = res;
    float v2 = res * res;
    #pragma unroll
    for (int o = 16; o; o >>= 1) {
        v  += __shfl_xor_sync(0xFFFFFFFFu, v,  o);
        v2 += __shfl_xor_sync(0xFFFFFFFFu, v2, o);
    }
    if (lane == 0) { s_red[head] = v; s_red[NH + head] = v2; }
    __syncthreads();

    float sum = 0.0f, sum2 = 0.0f;
    #pragma unroll
    for (int i = 0; i < NH; i++) { sum += s_red[i]; sum2 += s_red[NH + i]; }
    const float mu   = sum * (1.0f / ED);
    const float var  = sum2 * (1.0f / ED) - mu * mu;
    const float inv  = rsqrtf(var + EPSF);

    out[(((long)b * nq) + q) * ED + t] = (res - mu) * inv * ln_g[t] + ln_b[t];
}

// ---------------------------------------------------------------------------
extern "C" void kernel_launch(void* const* d_in, const int* in_sizes, int n_in,
                              void* d_out, int out_size) {
    const float* query  = (const float*)d_in[0];
    const float* feat   = (const float*)d_in[1];
    const float* ref2d  = (const float*)d_in[2];
    const float* W_off  = (const float*)d_in[3];
    const float* b_off  = (const float*)d_in[4];
    const float* W_attn = (const float*)d_in[5];
    const float* b_attn = (const float*)d_in[6];
    const float* ln_g   = (const float*)d_in[7];
    const float* ln_b   = (const float*)d_in[8];
    const int*   hp     = (const int*)d_in[9];
    const int*   wp     = (const int*)d_in[10];
    float* out = (float*)d_out;

    const int bs = in_sizes[0] / ED;           // 8
    const int nq = in_sizes[2] / (bs * 2);     // h*w = 4096

    sca_precompute_kernel<<<bs, 256>>>(query, W_off, b_off, W_attn, b_attn);

    dim3 grid(nq, bs);
    sca_main_kernel<<<grid, 256>>>(query, feat, ref2d, ln_g, ln_b, hp, wp, out, nq);
}

// round 4
// speedup vs baseline: 3.3041x; 3.3041x over previous
#include <cuda_runtime.h>

#define ED  256
#define NH  8
#define NP  8
#define D   32
#define EPSF 1e-5f
#define MAXB 8

// Per-batch packed (offx-0.5, offy-0.5, aw, 0) per (head, point)
__device__ float4 g_pack[MAXB * NH * NP];

// ---------------------------------------------------------------------------
// Precompute: off = relu(q @ W_off + b_off), aw = softmax_p(relu(q @ W_attn + b_attn))
// One block per batch; query is broadcast so this is per-batch only.
// Packs results as float4 {offx-0.5, offy-0.5, aw, 0}.
// ---------------------------------------------------------------------------
__global__ void sca_precompute_kernel(const float* __restrict__ query,
                                      const float* __restrict__ W_off,
                                      const float* __restrict__ b_off,
                                      const float* __restrict__ W_attn,
                                      const float* __restrict__ b_attn) {
    const int b = blockIdx.x;
    const int t = threadIdx.x;  // 0..255
    __shared__ float sq[ED];
    __shared__ float s_off[NH * NP * 2];
    __shared__ float s_aw[NH * NP];

    sq[t] = query[b * ED + t];
    __syncthreads();

    if (t < NH * NP * 2) {
        float acc = b_off[t];
        #pragma unroll 8
        for (int k = 0; k < ED; k++)
            acc = fmaf(sq[k], W_off[k * (NH * NP * 2) + t], acc);
        s_off[t] = fmaxf(acc, 0.0f);
    }
    if (t < NH * NP) {
        float acc = b_attn[t];
        #pragma unroll 8
        for (int k = 0; k < ED; k++)
            acc = fmaf(sq[k], W_attn[k * (NH * NP) + t], acc);
        s_aw[t] = fmaxf(acc, 0.0f);
    }
    __syncthreads();

    if (t < NH * NP) {
        const int g = t & ~(NP - 1);
        float m = -1e30f;
        #pragma unroll
        for (int i = 0; i < NP; i++) m = fmaxf(m, s_aw[g + i]);
        float s = 0.0f;
        #pragma unroll
        for (int i = 0; i < NP; i++) s += expf(s_aw[g + i] - m);
        const float aw = expf(s_aw[t] - m) / s;
        g_pack[b * NH * NP + t] = make_float4(s_off[2 * t] - 0.5f,
                                              s_off[2 * t + 1] - 0.5f,
                                              aw, 0.0f);
    }
}

// ---------------------------------------------------------------------------
// Main: bilinear gather + weighted sum + residual + LayerNorm.
// Block: 256 threads = 8 warps. 2 warps per query (4 queries/block).
// Warp covers 128 channels = 4 heads; lane handles 4 channels (float4).
// Grid: (nq/4, bs).
// ---------------------------------------------------------------------------
__global__ __launch_bounds__(256) void sca_main_kernel(
    const float* __restrict__ query,   // [bs, ED]
    const float* __restrict__ feat,    // [bs, nq, NH, D]
    const float* __restrict__ ref2d,   // [bs, nq, 2]
    const float* __restrict__ ln_g,
    const float* __restrict__ ln_b,
    const int*   __restrict__ hp,
    const int*   __restrict__ wp,
    float* __restrict__ out,           // [bs, nq, ED]
    int nq)
{
    const int t    = threadIdx.x;
    const int ww   = t >> 5;           // warp in block: 0..7
    const int lane = t & 31;
    const int slot = ww >> 1;          // query slot in block: 0..3
    const int half = ww & 1;           // which 128-channel half
    const int b    = blockIdx.y;

    int q = blockIdx.x * 4 + slot;
    if (q >= nq) q = nq - 1;           // duplicate work; deterministic & safe

    const int head = half * 4 + (lane >> 3);   // 0..7
    const int sub  = lane & 7;                 // 0..7
    const int ch   = head * D + sub * 4;       // channel base (multiple of 4)

    __shared__ float4 s_pack[NH * NP];
    __shared__ float  s_red[16];

    if (t < NH * NP) s_pack[t] = g_pack[b * NH * NP + t];
    __syncthreads();

    const int w = *wp;
    const int h = *hp;
    const float fw = (float)w;
    const float fh = (float)h;

    const float2 rr = __ldg((const float2*)(ref2d + ((long)b * nq + q) * 2));

    const float* fbase = feat + ((long)b * nq) * ED + ch;

    float4 acc = make_float4(0.f, 0.f, 0.f, 0.f);

    #pragma unroll
    for (int p = 0; p < NP; p++) {
        const float4 pk = s_pack[head * NP + p];

        // pixel coords: x = rx*w + offx - 0.5 (normalizer cancels)
        const float x = fmaf(rr.x, fw, pk.x);
        const float y = fmaf(rr.y, fh, pk.y);

        const float x0f = floorf(x);
        const float y0f = floorf(y);
        const float fx = x - x0f;
        const float fy = y - y0f;
        const int x0 = (int)x0f;
        const int y0 = (int)y0f;

        const bool vx0 = (unsigned)x0       < (unsigned)w;
        const bool vx1 = (unsigned)(x0 + 1) < (unsigned)w;
        const bool vy0 = (unsigned)y0       < (unsigned)h;
        const bool vy1 = (unsigned)(y0 + 1) < (unsigned)h;

        const int pix00 = y0 * w + x0;
        const int pix10 = pix00 + w;

        float4 s00 = make_float4(0.f, 0.f, 0.f, 0.f);
        float4 s01 = s00, s10 = s00, s11 = s00;
        if (vy0 & vx0) s00 = __ldg((const float4*)(fbase + (long)pix00 * ED));
        if (vy0 & vx1) s01 = __ldg((const float4*)(fbase + (long)(pix00 + 1) * ED));
        if (vy1 & vx0) s10 = __ldg((const float4*)(fbase + (long)pix10 * ED));
        if (vy1 & vx1) s11 = __ldg((const float4*)(fbase + (long)(pix10 + 1) * ED));

        const float omx = 1.0f - fx;
        const float omy = 1.0f - fy;
        const float a0  = pk.z * omy;
        const float a1  = pk.z * fy;
        const float w00 = a0 * omx, w01 = a0 * fx;
        const float w10 = a1 * omx, w11 = a1 * fx;

        acc.x = fmaf(w00, s00.x, fmaf(w01, s01.x, fmaf(w10, s10.x, fmaf(w11, s11.x, acc.x))));
        acc.y = fmaf(w00, s00.y, fmaf(w01, s01.y, fmaf(w10, s10.y, fmaf(w11, s11.y, acc.y))));
        acc.z = fmaf(w00, s00.z, fmaf(w01, s01.z, fmaf(w10, s10.z, fmaf(w11, s11.z, acc.z))));
        acc.w = fmaf(w00, s00.w, fmaf(w01, s01.w, fmaf(w10, s10.w, fmaf(w11, s11.w, acc.w))));
    }

    // residual with broadcast query
    const float4 qv = __ldg((const float4*)(query + b * ED + ch));
    float4 res;
    res.x = acc.x + qv.x;
    res.y = acc.y + qv.y;
    res.z = acc.z + qv.z;
    res.w = acc.w + qv.w;

    // LayerNorm over ED=256 (2 warps per query)
    float sum  = res.x + res.y + res.z + res.w;
    float sum2 = res.x * res.x + res.y * res.y + res.z * res.z + res.w * res.w;
    #pragma unroll
    for (int o = 16; o; o >>= 1) {
        sum  += __shfl_xor_sync(0xFFFFFFFFu, sum,  o);
        sum2 += __shfl_xor_sync(0xFFFFFFFFu, sum2, o);
    }
    if (lane == 0) { s_red[ww] = sum; s_red[8 + ww] = sum2; }
    __syncthreads();

    const float S  = s_red[slot * 2]     + s_red[slot * 2 + 1];
    const float S2 = s_red[8 + slot * 2] + s_red[8 + slot * 2 + 1];
    const float mu  = S * (1.0f / ED);
    const float var = S2 * (1.0f / ED) - mu * mu;
    const float inv = rsqrtf(var + EPSF);

    const float4 gg = __ldg((const float4*)(ln_g + ch));
    const float4 bb = __ldg((const float4*)(ln_b + ch));
    float4 o4;
    o4.x = (res.x - mu) * inv * gg.x + bb.x;
    o4.y = (res.y - mu) * inv * gg.y + bb.y;
    o4.z = (res.z - mu) * inv * gg.z + bb.z;
    o4.w = (res.w - mu) * inv * gg.w + bb.w;

    *(float4*)(out + (((long)b * nq) + q) * ED + ch) = o4;
}

// ---------------------------------------------------------------------------
extern "C" void kernel_launch(void* const* d_in, const int* in_sizes, int n_in,
                              void* d_out, int out_size) {
    const float* query  = (const float*)d_in[0];
    const float* feat   = (const float*)d_in[1];
    const float* ref2d  = (const float*)d_in[2];
    const float* W_off  = (const float*)d_in[3];
    const float* b_off  = (const float*)d_in[4];
    const float* W_attn = (const float*)d_in[5];
    const float* b_attn = (const float*)d_in[6];
    const float* ln_g   = (const float*)d_in[7];
    const float* ln_b   = (const float*)d_in[8];
    const int*   hp     = (const int*)d_in[9];
    const int*   wp     = (const int*)d_in[10];
    float* out = (float*)d_out;

    const int bs = in_sizes[0] / ED;           // 8
    const int nq = in_sizes[2] / (bs * 2);     // h*w = 4096

    sca_precompute_kernel<<<bs, 256>>>(query, W_off, b_off, W_attn, b_attn);

    dim3 grid((nq + 3) / 4, bs);
    sca_main_kernel<<<grid, 256>>>(query, feat, ref2d, ln_g, ln_b, hp, wp, out, nq);
}